// round 1
// baseline (speedup 1.0000x reference)
#include <cuda_runtime.h>
#include <math.h>

#define NTOK 2048
#define DIMV 1024
#define NEXP 8
#define HDIM 2048

// ---------------- scratch (__device__ globals: no allocation allowed) ----------------
__device__ int   g_counts[NEXP];
__device__ int   g_offsets[NEXP];
__device__ int   g_perm[NEXP * NTOK];    // token id per (expert, local slot)
__device__ float g_pw[NEXP * NTOK];      // normalized combine weight per slot
__device__ float g_h[(size_t)2 * NTOK * HDIM];   // 4096 x 2048 fp32 = 32 MB

// ---------------- 0) zero output + counters ----------------
__global__ void zero_kernel(float* __restrict__ out) {
    int i = blockIdx.x * blockDim.x + threadIdx.x;
    if (i < NTOK * DIMV) out[i] = 0.f;
    if (i < NEXP) g_counts[i] = 0;
}

// ---------------- 1) gating: logits -> sigmoid -> top2 -> permutation ----------------
__global__ void gate_kernel(const float* __restrict__ x,
                            const float* __restrict__ gw,
                            const float* __restrict__ bias) {
    int t = blockIdx.x;
    const float* xr = x + (size_t)t * DIMV;

    float acc[NEXP];
#pragma unroll
    for (int e = 0; e < NEXP; e++) acc[e] = 0.f;

    for (int d = threadIdx.x; d < DIMV; d += blockDim.x) {
        float xv = xr[d];
#pragma unroll
        for (int e = 0; e < NEXP; e++) acc[e] += xv * gw[e * DIMV + d];
    }

    __shared__ float sred[256][NEXP + 1];
#pragma unroll
    for (int e = 0; e < NEXP; e++) sred[threadIdx.x][e] = acc[e];
    __syncthreads();
    for (int s = 128; s > 0; s >>= 1) {
        if (threadIdx.x < s) {
#pragma unroll
            for (int e = 0; e < NEXP; e++)
                sred[threadIdx.x][e] += sred[threadIdx.x + s][e];
        }
        __syncthreads();
    }

    if (threadIdx.x == 0) {
        float sc[NEXP];
#pragma unroll
        for (int e = 0; e < NEXP; e++)
            sc[e] = 1.f / (1.f + __expf(-(sred[0][e] + bias[e])));

        // top-2, strict > so ties keep the lowest index (matches jax.lax.top_k)
        int i0 = 0;
#pragma unroll
        for (int e = 1; e < NEXP; e++) if (sc[e] > sc[i0]) i0 = e;
        int i1 = (i0 == 0) ? 1 : 0;
#pragma unroll
        for (int e = 0; e < NEXP; e++)
            if (e != i0 && sc[e] > sc[i1]) i1 = e;

        float s0 = sc[i0], s1 = sc[i1];
        float inv = 1.f / (s0 + s1 + 1e-6f);

        int slot0 = atomicAdd(&g_counts[i0], 1);
        g_perm[i0 * NTOK + slot0] = t;
        g_pw[i0 * NTOK + slot0]   = s0 * inv;
        int slot1 = atomicAdd(&g_counts[i1], 1);
        g_perm[i1 * NTOK + slot1] = t;
        g_pw[i1 * NTOK + slot1]   = s1 * inv;
    }
}

// ---------------- 2) exclusive scan of expert counts ----------------
__global__ void offsets_kernel() {
    if (threadIdx.x == 0) {
        int s = 0;
        for (int e = 0; e < NEXP; e++) { g_offsets[e] = s; s += g_counts[e]; }
    }
}

// ---------------- 3) GEMM1: h = silu(x_gathered @ w1[e]^T) ----------------
// A: gathered x rows [cnt, 1024] (K-contig), B: w1[e] [2048, 1024] (K-contig)
// tile 64x64x16, 256 threads, 4x4 microtile
__global__ void __launch_bounds__(256) gemm1_kernel(const float* __restrict__ x,
                                                    const float* __restrict__ w1) {
    int e   = blockIdx.z;
    int cnt = g_counts[e];
    int m0  = blockIdx.y * 64;
    if (m0 >= cnt) return;
    int n0  = blockIdx.x * 64;
    int off = g_offsets[e];
    const float* B = w1 + (size_t)e * HDIM * DIMV;

    __shared__ float As[16][68];
    __shared__ float Bs[16][68];

    int tid = threadIdx.x;
    int lr  = tid & 63;   // tile row for loads
    int lk  = tid >> 6;   // 0..3 -> which float4 along K

    int arow = m0 + lr;
    int tokA = (arow < cnt) ? g_perm[e * NTOK + arow] : -1;
    const float4* aptr = (tokA >= 0)
        ? reinterpret_cast<const float4*>(x + (size_t)tokA * DIMV) : nullptr;
    const float4* bptr = reinterpret_cast<const float4*>(B + (size_t)(n0 + lr) * DIMV);

    float acc[4][4];
#pragma unroll
    for (int i = 0; i < 4; i++)
#pragma unroll
        for (int j = 0; j < 4; j++) acc[i][j] = 0.f;

    int rm = (tid & 15) * 4;
    int rn = (tid >> 4) * 4;

    for (int k0 = 0; k0 < DIMV; k0 += 16) {
        float4 av = make_float4(0.f, 0.f, 0.f, 0.f);
        if (aptr) av = aptr[(k0 >> 2) + lk];
        float4 bv = bptr[(k0 >> 2) + lk];
        As[lk * 4 + 0][lr] = av.x;
        As[lk * 4 + 1][lr] = av.y;
        As[lk * 4 + 2][lr] = av.z;
        As[lk * 4 + 3][lr] = av.w;
        Bs[lk * 4 + 0][lr] = bv.x;
        Bs[lk * 4 + 1][lr] = bv.y;
        Bs[lk * 4 + 2][lr] = bv.z;
        Bs[lk * 4 + 3][lr] = bv.w;
        __syncthreads();
#pragma unroll
        for (int k = 0; k < 16; k++) {
            float a[4], b[4];
#pragma unroll
            for (int i = 0; i < 4; i++) a[i] = As[k][rm + i];
#pragma unroll
            for (int j = 0; j < 4; j++) b[j] = Bs[k][rn + j];
#pragma unroll
            for (int i = 0; i < 4; i++)
#pragma unroll
                for (int j = 0; j < 4; j++) acc[i][j] = fmaf(a[i], b[j], acc[i][j]);
        }
        __syncthreads();
    }

#pragma unroll
    for (int i = 0; i < 4; i++) {
        int r = m0 + rm + i;
        if (r < cnt) {
            float* hrow = g_h + (size_t)(off + r) * HDIM + n0 + rn;
#pragma unroll
            for (int j = 0; j < 4; j++) {
                float v = acc[i][j];
                hrow[j] = v / (1.f + __expf(-v));   // silu
            }
        }
    }
}

// ---------------- 4) GEMM2: out[tok] += w * (h @ w2[e]^T) ----------------
// A: g_h rows [cnt, 2048] (K-contig), B: w2[e] [1024, 2048] (K-contig)
__global__ void __launch_bounds__(256) gemm2_kernel(const float* __restrict__ w2,
                                                    float* __restrict__ out) {
    int e   = blockIdx.z;
    int cnt = g_counts[e];
    int m0  = blockIdx.y * 64;
    if (m0 >= cnt) return;
    int n0  = blockIdx.x * 64;
    int off = g_offsets[e];
    const float* B = w2 + (size_t)e * DIMV * HDIM;

    __shared__ float As[16][68];
    __shared__ float Bs[16][68];

    int tid = threadIdx.x;
    int lr  = tid & 63;
    int lk  = tid >> 6;

    int arow = m0 + lr;
    const float4* aptr = (arow < cnt)
        ? reinterpret_cast<const float4*>(g_h + (size_t)(off + arow) * HDIM) : nullptr;
    const float4* bptr = reinterpret_cast<const float4*>(B + (size_t)(n0 + lr) * HDIM);

    float acc[4][4];
#pragma unroll
    for (int i = 0; i < 4; i++)
#pragma unroll
        for (int j = 0; j < 4; j++) acc[i][j] = 0.f;

    int rm = (tid & 15) * 4;
    int rn = (tid >> 4) * 4;

    for (int k0 = 0; k0 < HDIM; k0 += 16) {
        float4 av = make_float4(0.f, 0.f, 0.f, 0.f);
        if (aptr) av = aptr[(k0 >> 2) + lk];
        float4 bv = bptr[(k0 >> 2) + lk];
        As[lk * 4 + 0][lr] = av.x;
        As[lk * 4 + 1][lr] = av.y;
        As[lk * 4 + 2][lr] = av.z;
        As[lk * 4 + 3][lr] = av.w;
        Bs[lk * 4 + 0][lr] = bv.x;
        Bs[lk * 4 + 1][lr] = bv.y;
        Bs[lk * 4 + 2][lr] = bv.z;
        Bs[lk * 4 + 3][lr] = bv.w;
        __syncthreads();
#pragma unroll
        for (int k = 0; k < 16; k++) {
            float a[4], b[4];
#pragma unroll
            for (int i = 0; i < 4; i++) a[i] = As[k][rm + i];
#pragma unroll
            for (int j = 0; j < 4; j++) b[j] = Bs[k][rn + j];
#pragma unroll
            for (int i = 0; i < 4; i++)
#pragma unroll
                for (int j = 0; j < 4; j++) acc[i][j] = fmaf(a[i], b[j], acc[i][j]);
        }
        __syncthreads();
    }

#pragma unroll
    for (int i = 0; i < 4; i++) {
        int r = m0 + rm + i;
        if (r < cnt) {
            int   tok = g_perm[e * NTOK + r];
            float w   = g_pw[e * NTOK + r];
            float* orow = out + (size_t)tok * DIMV + n0 + rn;
#pragma unroll
            for (int j = 0; j < 4; j++) atomicAdd(&orow[j], w * acc[i][j]);
        }
    }
}

// ---------------- launch ----------------
extern "C" void kernel_launch(void* const* d_in, const int* in_sizes, int n_in,
                              void* d_out, int out_size) {
    const float* x      = (const float*)d_in[0];   // [1,2048,1024]
    const float* gate_w = (const float*)d_in[1];   // [8,1024]
    const float* bias   = (const float*)d_in[2];   // [8]
    const float* w1     = (const float*)d_in[3];   // [8,2048,1024]
    const float* w2     = (const float*)d_in[4];   // [8,1024,2048]
    float* out          = (float*)d_out;           // [1,2048,1024]

    zero_kernel<<<(NTOK * DIMV + 255) / 256, 256>>>(out);
    gate_kernel<<<NTOK, 256>>>(x, gate_w, bias);
    offsets_kernel<<<1, 32>>>();
    gemm1_kernel<<<dim3(HDIM / 64, NTOK / 64, NEXP), 256>>>(x, w1);
    gemm2_kernel<<<dim3(DIMV / 64, NTOK / 64, NEXP), 256>>>(w2, out);
}